// round 10
// baseline (speedup 1.0000x reference)
#include <cuda_runtime.h>

#define N_Z    8192
#define N_E    16384
#define N_EMBS 16
#define M_PER  1024
#define TPB    256
#define MG     8          // m-groups: 128 columns per block
#define NSL    64         // i-slices of 128
#define ICH    128
#define NBLK   (MG * NSL) // 512 blocks, all co-resident at 4 blocks/SM

// Scratch (__device__ globals; no allocation allowed)
__device__ float g_part[NSL][N_EMBS][M_PER];  // partial S per (slice,k,m)  (4MB)
__device__ float g_bsum[64];
__device__ int   g_bar1 = 0;
__device__ int   g_bar2 = 0;

__device__ __forceinline__ float ex2(float x) {
    float r; asm("ex2.approx.f32 %0, %1;" : "=f"(r) : "f"(x)); return r;
}
__device__ __forceinline__ unsigned long long fma2(unsigned long long a,
                                                   unsigned long long b,
                                                   unsigned long long c) {
    unsigned long long d;
    asm("fma.rn.f32x2 %0, %1, %2, %3;" : "=l"(d) : "l"(a), "l"(b), "l"(c));
    return d;
}

// ---------------------------------------------------------------------------
// Single persistent kernel, k-split variant.
// Block (mg, sl): 256 threads = 128 m-columns x 2 k-halves.
// Each thread accumulates 8 of the 16 k's for one m over 128 i:
//   acc_k[m] += G[i][k] * D[i][m],  G = exp2(a_i + b_i.u_k), D = exp2(b_i.v_m)
// Grid barrier (512 blocks, guaranteed 4/SM by launch_bounds).
// Phase 2: blocks 0..63 reduce slices, apply C in log domain -> lse.
// Phase 3: block 0 folds 64 sums -> loss scalar.
// ---------------------------------------------------------------------------
__global__ void __launch_bounds__(TPB, 4) fused_kernel(
        const float* __restrict__ z,
        const float* __restrict__ emb,
        const float* __restrict__ log_sigma,
        const float* __restrict__ eps,
        const float* __restrict__ temp,
        float* __restrict__ out) {
    __shared__ float4 s_G[ICH][4];    // 16 G values per i (as 4 float4)
    __shared__ float2 s_b[ICH];       // (b0,b1) per i
    __shared__ float  red[8];

    const int tid = threadIdx.x;
    const int mg  = blockIdx.x;       // 0..7
    const int sl  = blockIdx.y;       // 0..63
    const int bid = sl * MG + mg;

    const float T  = __ldg(temp);
    const float ls = __ldg(log_sigma);
    const float LOG2E = 1.4426950408889634f;
    const float LN2   = 0.6931471805599453f;
    const float al  = -0.5f * LOG2E * __expf(-2.0f * ls);  // alpha*log2e
    const float omT = 1.0f - T;

    // ---- stage: 2 threads per i (each does 8 of the 16 k's) ----
    {
        int il = tid >> 1;
        int hh = tid & 1;
        int i  = sl * ICH + il;
        float z0 = z[2 * i + 0], z1 = z[2 * i + 1];
        float a  = al * (z0 * z0 + z1 * z1);
        float b0 = -2.0f * al * z0;
        float b1 = -2.0f * al * z1;
        if (hh == 0) s_b[il] = make_float2(b0, b1);
        float g[8];
#pragma unroll
        for (int kk = 0; kk < 8; ++kk) {
            int k = hh * 8 + kk;
            float u0 = omT * emb[2 * k + 0];
            float u1 = omT * emb[2 * k + 1];
            g[kk] = ex2(fmaf(b1, u1, fmaf(b0, u0, a)));
        }
        s_G[il][2 * hh + 0] = make_float4(g[0], g[1], g[2], g[3]);
        s_G[il][2 * hh + 1] = make_float4(g[4], g[5], g[6], g[7]);
    }

    // ---- thread -> (m, k-half) mapping: warps 0-3 h=0, warps 4-7 h=1 ----
    const int mlocal = tid & 127;
    const int h      = tid >> 7;             // uniform within a warp
    const int m      = mg * 128 + mlocal;
    const float v0 = T * eps[2 * m + 0];
    const float v1 = T * eps[2 * m + 1];
    __syncthreads();

    // ---- main loop: 128 i, 8 k-accumulators packed as 4 f32x2 ----
    unsigned long long acc0 = 0ULL, acc1 = 0ULL, acc2 = 0ULL, acc3 = 0ULL;

#pragma unroll 8
    for (int t = 0; t < ICH; ++t) {
        float2 b = s_b[t];                          // broadcast LDS.64
        float D = ex2(fmaf(b.y, v1, b.x * v0));
        unsigned int Du = __float_as_uint(D);
        unsigned long long D2;
        asm("mov.b64 %0, {%1, %2};" : "=l"(D2) : "r"(Du), "r"(Du));
        const ulonglong2* G = reinterpret_cast<const ulonglong2*>(&s_G[t][0]);
        ulonglong2 gA = G[2 * h + 0];               // broadcast LDS.128
        ulonglong2 gB = G[2 * h + 1];
        acc0 = fma2(gA.x, D2, acc0);
        acc1 = fma2(gA.y, D2, acc1);
        acc2 = fma2(gB.x, D2, acc2);
        acc3 = fma2(gB.y, D2, acc3);
    }

    // ---- write partials (unique slots -> deterministic, coalesced in m) ----
    {
        unsigned int lo, hi;
        asm("mov.b64 {%0, %1}, %2;" : "=r"(lo), "=r"(hi) : "l"(acc0));
        g_part[sl][8 * h + 0][m] = __uint_as_float(lo);
        g_part[sl][8 * h + 1][m] = __uint_as_float(hi);
        asm("mov.b64 {%0, %1}, %2;" : "=r"(lo), "=r"(hi) : "l"(acc1));
        g_part[sl][8 * h + 2][m] = __uint_as_float(lo);
        g_part[sl][8 * h + 3][m] = __uint_as_float(hi);
        asm("mov.b64 {%0, %1}, %2;" : "=r"(lo), "=r"(hi) : "l"(acc2));
        g_part[sl][8 * h + 4][m] = __uint_as_float(lo);
        g_part[sl][8 * h + 5][m] = __uint_as_float(hi);
        asm("mov.b64 {%0, %1}, %2;" : "=r"(lo), "=r"(hi) : "l"(acc3));
        g_part[sl][8 * h + 6][m] = __uint_as_float(lo);
        g_part[sl][8 * h + 7][m] = __uint_as_float(hi);
    }

    // ---- grid barrier 1 (all 512 blocks co-resident: launch_bounds(256,4)) ----
    __syncthreads();
    if (tid == 0) {
        __threadfence();
        atomicAdd(&g_bar1, 1);
        while (*(volatile int*)&g_bar1 < NBLK) __nanosleep(32);
    }
    __syncthreads();

    // ---- phase 2: 64 blocks, 256 columns each ----
    if (bid < 64) {
        int j  = bid * TPB + tid;
        int k  = j >> 10;
        int mm = j & (M_PER - 1);
        float S = 0.0f;
#pragma unroll
        for (int s = 0; s < NSL; ++s)
            S += __ldcg(&g_part[s][k][mm]);
        float u0 = omT * emb[2 * k + 0], u1 = omT * emb[2 * k + 1];
        float w0 = u0 + T * eps[2 * mm + 0];
        float w1 = u1 + T * eps[2 * mm + 1];
        float lse = LN2 * (al * (w0 * w0 + w1 * w1)) + __logf(S);

#pragma unroll
        for (int o = 16; o > 0; o >>= 1)
            lse += __shfl_xor_sync(0xffffffffu, lse, o);
        if ((tid & 31) == 0) red[tid >> 5] = lse;
        __syncthreads();
        if (tid == 0) {
            float v = red[0];
#pragma unroll
            for (int w = 1; w < 8; ++w) v += red[w];
            g_bsum[bid] = v;
        }
    }

    // ---- barrier 2 + final fold by block 0 ----
    __syncthreads();
    if (tid == 0) {
        __threadfence();
        atomicAdd(&g_bar2, 1);
        if (bid == 0) {
            while (*(volatile int*)&g_bar2 < NBLK) __nanosleep(32);
            float v = 0.0f;
#pragma unroll
            for (int b = 0; b < 64; ++b) v += __ldcg(&g_bsum[b]);
            // loss = -mean(lse) + 0.5*z_dim*(2*ls - 1) + log(N), z_dim = 2
            out[0] = -v / (float)N_E + (2.0f * ls - 1.0f) + logf((float)N_Z);
            g_bar1 = 0;                       // reset for next graph replay
            g_bar2 = 0;
            __threadfence();
        }
    }
}

// ---------------------------------------------------------------------------
extern "C" void kernel_launch(void* const* d_in, const int* in_sizes, int n_in,
                              void* d_out, int out_size) {
    const float* z    = (const float*)d_in[0];
    const float* emb  = (const float*)d_in[1];
    const float* ls   = (const float*)d_in[2];
    const float* eps  = (const float*)d_in[3];
    const float* temp = (const float*)d_in[4];
    float* out = (float*)d_out;

    dim3 grid(MG, NSL);                       // (8, 64) = 512 blocks
    fused_kernel<<<grid, TPB>>>(z, emb, ls, eps, temp, out);
}

// round 12
// speedup vs baseline: 1.0061x; 1.0061x over previous
#include <cuda_runtime.h>

#define N_Z    8192
#define N_E    16384
#define N_EMBS 16
#define M_PER  1024
#define TPB    128
#define MG     8          // m-groups of 128 columns
#define NSL    128        // i-slices of 64
#define ICH    64
#define FBLK   128        // finish blocks

// Scratch (__device__ globals; no allocation allowed)
__device__ float g_part[NSL][N_EMBS][M_PER];  // partial S per (slice,k,m)  (8MB)
__device__ float g_bsum[FBLK];
__device__ int   g_cnt = 0;

__device__ __forceinline__ float ex2(float x) {
    float r; asm("ex2.approx.f32 %0, %1;" : "=f"(r) : "f"(x)); return r;
}
__device__ __forceinline__ unsigned long long fma2(unsigned long long a,
                                                   unsigned long long b,
                                                   unsigned long long c) {
    unsigned long long d;
    asm("fma.rn.f32x2 %0, %1, %2, %3;" : "=l"(d) : "l"(a), "l"(b), "l"(c));
    return d;
}

// ---------------------------------------------------------------------------
// Main: block (mg, sl) = 128 m-columns x 64 i-rows.
// Thread owns one m, all 16 k's (8 packed f32x2 accumulators):
//   acc_k[m] += G[i][k] * D[i][m],  G = exp2(a_i + b_i.u_k), D = exp2(b_i.v_m)
// No launch bounds cap: ptxas gets registers for deep software pipelining,
// and 1024 blocks give ~7 warps/SMSP without any co-residency requirement.
// ---------------------------------------------------------------------------
__global__ void main_kernel(
        const float* __restrict__ z,
        const float* __restrict__ emb,
        const float* __restrict__ log_sigma,
        const float* __restrict__ eps,
        const float* __restrict__ temp) {
    __shared__ float4 s_G[ICH][4];    // 16 G values per i (as 4 float4)
    __shared__ float2 s_b[ICH];       // (b0,b1) per i

    const int tid = threadIdx.x;
    const int mg  = blockIdx.x;       // 0..7
    const int sl  = blockIdx.y;       // 0..127

    const float T  = __ldg(temp);
    const float ls = __ldg(log_sigma);
    const float LOG2E = 1.4426950408889634f;
    const float al  = -0.5f * LOG2E * __expf(-2.0f * ls);  // alpha*log2e
    const float omT = 1.0f - T;

    // ---- stage: 2 threads per i (each does 8 of the 16 k's) ----
    {
        int il = tid >> 1;            // 0..63
        int hh = tid & 1;
        int i  = sl * ICH + il;
        float z0 = z[2 * i + 0], z1 = z[2 * i + 1];
        float a  = al * (z0 * z0 + z1 * z1);
        float b0 = -2.0f * al * z0;
        float b1 = -2.0f * al * z1;
        if (hh == 0) s_b[il] = make_float2(b0, b1);
        float g[8];
#pragma unroll
        for (int kk = 0; kk < 8; ++kk) {
            int k = hh * 8 + kk;
            float u0 = omT * emb[2 * k + 0];
            float u1 = omT * emb[2 * k + 1];
            g[kk] = ex2(fmaf(b1, u1, fmaf(b0, u0, a)));
        }
        s_G[il][2 * hh + 0] = make_float4(g[0], g[1], g[2], g[3]);
        s_G[il][2 * hh + 1] = make_float4(g[4], g[5], g[6], g[7]);
    }

    const int m  = mg * TPB + tid;                 // this thread's column
    const float v0 = T * eps[2 * m + 0];
    const float v1 = T * eps[2 * m + 1];
    __syncthreads();

    // ---- main loop: 64 i, 16 k-accumulators packed as 8 f32x2 ----
    unsigned long long acc[8];
#pragma unroll
    for (int p = 0; p < 8; ++p) acc[p] = 0ULL;

#pragma unroll 8
    for (int t = 0; t < ICH; ++t) {
        float2 b = s_b[t];                          // broadcast LDS.64
        float D = ex2(fmaf(b.y, v1, b.x * v0));
        unsigned int Du = __float_as_uint(D);
        unsigned long long D2;
        asm("mov.b64 %0, {%1, %2};" : "=l"(D2) : "r"(Du), "r"(Du));
        const ulonglong2* G = reinterpret_cast<const ulonglong2*>(&s_G[t][0]);
        ulonglong2 gA = G[0], gB = G[1], gC = G[2], gD = G[3];
        acc[0] = fma2(gA.x, D2, acc[0]);
        acc[1] = fma2(gA.y, D2, acc[1]);
        acc[2] = fma2(gB.x, D2, acc[2]);
        acc[3] = fma2(gB.y, D2, acc[3]);
        acc[4] = fma2(gC.x, D2, acc[4]);
        acc[5] = fma2(gC.y, D2, acc[5]);
        acc[6] = fma2(gD.x, D2, acc[6]);
        acc[7] = fma2(gD.y, D2, acc[7]);
    }

    // ---- write partials (unique slots -> deterministic, coalesced in m) ----
#pragma unroll
    for (int p = 0; p < 8; ++p) {
        unsigned int lo, hi;
        asm("mov.b64 {%0, %1}, %2;" : "=r"(lo), "=r"(hi) : "l"(acc[p]));
        g_part[sl][2 * p + 0][m] = __uint_as_float(lo);
        g_part[sl][2 * p + 1][m] = __uint_as_float(hi);
    }
}

// ---------------------------------------------------------------------------
// Finish: per column j=(k,m): S_j = sum over 128 slices, apply C_{k,m} in
// log domain -> lse_j. Block-reduce; last block folds 128 block sums.
// ---------------------------------------------------------------------------
__global__ void __launch_bounds__(TPB) finish_kernel(
        const float* __restrict__ emb,
        const float* __restrict__ log_sigma,
        const float* __restrict__ eps,
        const float* __restrict__ temp,
        float* __restrict__ out) {
    __shared__ float red[4];
    __shared__ int s_last;

    const int tid = threadIdx.x;
    const int j   = blockIdx.x * TPB + tid;   // 0..16383
    const int k   = j >> 10;
    const int mm  = j & (M_PER - 1);

    const float T  = __ldg(temp);
    const float ls = __ldg(log_sigma);
    const float LOG2E = 1.4426950408889634f;
    const float LN2   = 0.6931471805599453f;
    const float al  = -0.5f * LOG2E * __expf(-2.0f * ls);
    const float omT = 1.0f - T;

    float S = 0.0f;
#pragma unroll
    for (int s = 0; s < NSL; ++s)
        S += g_part[s][k][mm];

    float w0 = omT * emb[2 * k + 0] + T * eps[2 * mm + 0];
    float w1 = omT * emb[2 * k + 1] + T * eps[2 * mm + 1];
    float lse = LN2 * (al * (w0 * w0 + w1 * w1)) + __logf(S);

    // block reduction (128 threads)
#pragma unroll
    for (int o = 16; o > 0; o >>= 1)
        lse += __shfl_xor_sync(0xffffffffu, lse, o);
    if ((tid & 31) == 0) red[tid >> 5] = lse;
    __syncthreads();
    if (tid == 0) {
        g_bsum[blockIdx.x] = red[0] + red[1] + red[2] + red[3];
        __threadfence();
        int prev = atomicAdd(&g_cnt, 1);
        s_last = (prev == FBLK - 1) ? 1 : 0;
    }
    __syncthreads();

    if (s_last) {
        __threadfence();
        float v = g_bsum[tid];                // 128 threads, one each
#pragma unroll
        for (int o = 16; o > 0; o >>= 1)
            v += __shfl_xor_sync(0xffffffffu, v, o);
        if ((tid & 31) == 0) red[tid >> 5] = v;
        __syncthreads();
        if (tid == 0) {
            float tot = red[0] + red[1] + red[2] + red[3];
            // loss = -mean(lse) + 0.5*z_dim*(2*ls - 1) + log(N), z_dim = 2
            out[0] = -tot / (float)N_E + (2.0f * ls - 1.0f) + logf((float)N_Z);
            g_cnt = 0;                        // reset for next graph replay
        }
    }
}

// ---------------------------------------------------------------------------
extern "C" void kernel_launch(void* const* d_in, const int* in_sizes, int n_in,
                              void* d_out, int out_size) {
    const float* z    = (const float*)d_in[0];
    const float* emb  = (const float*)d_in[1];
    const float* ls   = (const float*)d_in[2];
    const float* eps  = (const float*)d_in[3];
    const float* temp = (const float*)d_in[4];
    float* out = (float*)d_out;

    dim3 grid(MG, NSL);                       // (8, 128) = 1024 blocks
    main_kernel<<<grid, TPB>>>(z, emb, ls, eps, temp);
    finish_kernel<<<FBLK, TPB>>>(emb, ls, eps, temp, out);
}

// round 17
// speedup vs baseline: 1.1081x; 1.1014x over previous
#include <cuda_runtime.h>

#define N_Z    8192
#define N_E    16384
#define N_EMBS 16
#define M_PER  1024
#define TPB    128
#define MG     8          // m-groups of 128 columns
#define NSL    128        // i-slices of 64
#define ICH    64
#define FBLK   128        // finish blocks
#define FTPB   512        // finish threads: 128 cols x 4 slice-groups
#define SG     4
#define SLG    (NSL / SG) // 32 slices per group

// Scratch (__device__ globals; no allocation allowed)
__device__ float g_part[NSL][N_EMBS][M_PER];  // partial S per (slice,k,m)  (8MB)
__device__ float g_bsum[FBLK];
__device__ int   g_cnt = 0;

__device__ __forceinline__ float ex2(float x) {
    float r; asm("ex2.approx.f32 %0, %1;" : "=f"(r) : "f"(x)); return r;
}
__device__ __forceinline__ unsigned long long fma2(unsigned long long a,
                                                   unsigned long long b,
                                                   unsigned long long c) {
    unsigned long long d;
    asm("fma.rn.f32x2 %0, %1, %2, %3;" : "=l"(d) : "l"(a), "l"(b), "l"(c));
    return d;
}

// ---------------------------------------------------------------------------
// Main: block (mg, sl) = 128 m-columns x 64 i-rows.  (unchanged from R12)
// Thread owns one m, all 16 k's (8 packed f32x2 accumulators):
//   acc_k[m] += G[i][k] * D[i][m],  G = exp2(a_i + b_i.u_k), D = exp2(b_i.v_m)
// ---------------------------------------------------------------------------
__global__ void main_kernel(
        const float* __restrict__ z,
        const float* __restrict__ emb,
        const float* __restrict__ log_sigma,
        const float* __restrict__ eps,
        const float* __restrict__ temp) {
    __shared__ float4 s_G[ICH][4];    // 16 G values per i (as 4 float4)
    __shared__ float2 s_b[ICH];       // (b0,b1) per i

    const int tid = threadIdx.x;
    const int mg  = blockIdx.x;       // 0..7
    const int sl  = blockIdx.y;       // 0..127

    const float T  = __ldg(temp);
    const float ls = __ldg(log_sigma);
    const float LOG2E = 1.4426950408889634f;
    const float al  = -0.5f * LOG2E * __expf(-2.0f * ls);  // alpha*log2e
    const float omT = 1.0f - T;

    // ---- stage: 2 threads per i (each does 8 of the 16 k's) ----
    {
        int il = tid >> 1;            // 0..63
        int hh = tid & 1;
        int i  = sl * ICH + il;
        float z0 = z[2 * i + 0], z1 = z[2 * i + 1];
        float a  = al * (z0 * z0 + z1 * z1);
        float b0 = -2.0f * al * z0;
        float b1 = -2.0f * al * z1;
        if (hh == 0) s_b[il] = make_float2(b0, b1);
        float g[8];
#pragma unroll
        for (int kk = 0; kk < 8; ++kk) {
            int k = hh * 8 + kk;
            float u0 = omT * emb[2 * k + 0];
            float u1 = omT * emb[2 * k + 1];
            g[kk] = ex2(fmaf(b1, u1, fmaf(b0, u0, a)));
        }
        s_G[il][2 * hh + 0] = make_float4(g[0], g[1], g[2], g[3]);
        s_G[il][2 * hh + 1] = make_float4(g[4], g[5], g[6], g[7]);
    }

    const int m  = mg * TPB + tid;                 // this thread's column
    const float v0 = T * eps[2 * m + 0];
    const float v1 = T * eps[2 * m + 1];
    __syncthreads();

    // ---- main loop: 64 i, 16 k-accumulators packed as 8 f32x2 ----
    unsigned long long acc[8];
#pragma unroll
    for (int p = 0; p < 8; ++p) acc[p] = 0ULL;

#pragma unroll 8
    for (int t = 0; t < ICH; ++t) {
        float2 b = s_b[t];                          // broadcast LDS.64
        float D = ex2(fmaf(b.y, v1, b.x * v0));
        unsigned int Du = __float_as_uint(D);
        unsigned long long D2;
        asm("mov.b64 %0, {%1, %2};" : "=l"(D2) : "r"(Du), "r"(Du));
        const ulonglong2* G = reinterpret_cast<const ulonglong2*>(&s_G[t][0]);
        ulonglong2 gA = G[0], gB = G[1], gC = G[2], gD = G[3];
        acc[0] = fma2(gA.x, D2, acc[0]);
        acc[1] = fma2(gA.y, D2, acc[1]);
        acc[2] = fma2(gB.x, D2, acc[2]);
        acc[3] = fma2(gB.y, D2, acc[3]);
        acc[4] = fma2(gC.x, D2, acc[4]);
        acc[5] = fma2(gC.y, D2, acc[5]);
        acc[6] = fma2(gD.x, D2, acc[6]);
        acc[7] = fma2(gD.y, D2, acc[7]);
    }

    // ---- write partials (unique slots -> deterministic, coalesced in m) ----
#pragma unroll
    for (int p = 0; p < 8; ++p) {
        unsigned int lo, hi;
        asm("mov.b64 {%0, %1}, %2;" : "=r"(lo), "=r"(hi) : "l"(acc[p]));
        g_part[sl][2 * p + 0][m] = __uint_as_float(lo);
        g_part[sl][2 * p + 1][m] = __uint_as_float(hi);
    }
}

// ---------------------------------------------------------------------------
// Finish (4-way slice-group split): 128 blocks x 512 threads.
// Block b owns columns j in [b*128, b*128+128). Thread (sg = tid>>7,
// col = tid&127) sums 32 slices; smem combine; first 128 threads do
// lse_j = C*ln2 + log(S); block-reduce; last block folds 128 sums.
// ---------------------------------------------------------------------------
__global__ void __launch_bounds__(FTPB) finish_kernel(
        const float* __restrict__ emb,
        const float* __restrict__ log_sigma,
        const float* __restrict__ eps,
        const float* __restrict__ temp,
        float* __restrict__ out) {
    __shared__ float s_S[SG][TPB];
    __shared__ float red[4];
    __shared__ int s_last;

    const int tid = threadIdx.x;
    const int sg  = tid >> 7;                 // 0..3
    const int col = tid & 127;
    const int j   = blockIdx.x * TPB + col;   // 0..16383
    const int k   = j >> 10;
    const int mm  = j & (M_PER - 1);

    // partial slice sum: 32 independent coalesced loads (high MLP)
    float S = 0.0f;
#pragma unroll
    for (int s = 0; s < SLG; ++s)
        S += g_part[sg * SLG + s][k][mm];
    s_S[sg][col] = S;
    __syncthreads();

    float lse = 0.0f;
    if (tid < TPB) {
        const float T  = __ldg(temp);
        const float ls = __ldg(log_sigma);
        const float LOG2E = 1.4426950408889634f;
        const float LN2   = 0.6931471805599453f;
        const float al  = -0.5f * LOG2E * __expf(-2.0f * ls);
        const float omT = 1.0f - T;

        float Stot = s_S[0][col] + s_S[1][col] + s_S[2][col] + s_S[3][col];
        float w0 = omT * emb[2 * k + 0] + T * eps[2 * mm + 0];
        float w1 = omT * emb[2 * k + 1] + T * eps[2 * mm + 1];
        lse = LN2 * (al * (w0 * w0 + w1 * w1)) + __logf(Stot);

        // reduce 128 lse values (4 warps)
#pragma unroll
        for (int o = 16; o > 0; o >>= 1)
            lse += __shfl_xor_sync(0xffffffffu, lse, o);
        if ((tid & 31) == 0) red[tid >> 5] = lse;
    }
    __syncthreads();
    if (tid == 0) {
        g_bsum[blockIdx.x] = red[0] + red[1] + red[2] + red[3];
        __threadfence();
        int prev = atomicAdd(&g_cnt, 1);
        s_last = (prev == FBLK - 1) ? 1 : 0;
    }
    __syncthreads();

    if (s_last && tid < 128) {
        __threadfence();
        float v = g_bsum[tid];                // 128 threads, one each
#pragma unroll
        for (int o = 16; o > 0; o >>= 1)
            v += __shfl_xor_sync(0xffffffffu, v, o);
        if ((tid & 31) == 0) red[tid >> 5] = v;
        __syncwarp();
        if (tid == 0) {
            // wait for the other 3 warps' red[] entries via spin on smem is
            // not needed: use a narrow fence — reuse __syncthreads is unsafe
            // under divergence, so fold warp results serially instead.
        }
    }
    __syncthreads();                          // all 512 threads reach here
    if (s_last && tid == 0) {
        const float ls = __ldg(log_sigma);
        float tot = red[0] + red[1] + red[2] + red[3];
        // loss = -mean(lse) + 0.5*z_dim*(2*ls - 1) + log(N), z_dim = 2
        out[0] = -tot / (float)N_E + (2.0f * ls - 1.0f) + logf((float)N_Z);
        g_cnt = 0;                            // reset for next graph replay
    }
}

// ---------------------------------------------------------------------------
extern "C" void kernel_launch(void* const* d_in, const int* in_sizes, int n_in,
                              void* d_out, int out_size) {
    const float* z    = (const float*)d_in[0];
    const float* emb  = (const float*)d_in[1];
    const float* ls   = (const float*)d_in[2];
    const float* eps  = (const float*)d_in[3];
    const float* temp = (const float*)d_in[4];
    float* out = (float*)d_out;

    dim3 grid(MG, NSL);                       // (8, 128) = 1024 blocks
    main_kernel<<<grid, TPB>>>(z, emb, ls, eps, temp);
    finish_kernel<<<FBLK, FTPB>>>(emb, ls, eps, temp, out);
}